// round 14
// baseline (speedup 1.0000x reference)
#include <cuda_runtime.h>
#include <cuda_fp16.h>
#include <stdint.h>

// B=8, T=2048, C=1024, fp32 in/out.
//  qk = x @ [Wq;Wk]^T (+bias, q-half scaled 1/32), fp16, one GEMM
//  vT[b] = Wv @ x_b^T + bv, fp16 (forked stream, overlaps qk-proj/S)
//  P~ = exp(q k^T) causal->0 (fused epilogue + fused row partial sums),
//       triangular-compacted grid (no dead CTAs)
//  out = (P~ @ vT^T) / rowsum(P~)  -- rowsum summed from the 16 partials
//       directly in the PV epilogue (inv kernel removed)
// GEMM mainloop is the R11/R13 champion, untouched.

#define BATCH 8
#define SEQ   2048
#define CDIM  1024

__device__ __align__(16) __half g_xh[(long)BATCH * SEQ * CDIM];
__device__ __align__(16) __half g_wh[3][(long)CDIM * CDIM];   // Wq,Wk,Wv
__device__ __align__(16) __half g_qk[(long)BATCH * SEQ * 2 * CDIM]; // q | k
__device__ __align__(16) __half g_vt[(long)BATCH * CDIM * SEQ];
__device__ __align__(16) __half g_p [(long)BATCH * SEQ * SEQ];
// zero-initialized statically; S writes only entries j <= t/128, the rest
// stay 0 forever -> summing all 16 in PV is exact and deterministic
__device__ __align__(16) float  g_partial[(long)BATCH * SEQ * 16];

#define BM 128
#define BN 128
#define BK 64                  // 64 fp16 = 128 B per smem row
#define NTHREADS 256
#define NSTAGE 3
#define STAGE_BYTES 16384

#define SROW_OFF (NSTAGE * 32768)
#define SMEM_SZ (NSTAGE * 32768 + 2048)    // 100352 B -> 2 CTAs/SM

__device__ __forceinline__ uint32_t smem_u32(const void* p) {
    uint32_t r;
    asm("{ .reg .u64 t; cvta.to.shared.u64 t, %1; cvt.u32.u64 %0, t; }"
        : "=r"(r) : "l"(p));
    return r;
}

// swizzled byte offset of 16B chunk c (0..7) in 128B row r
__device__ __forceinline__ uint32_t swz(int r, int c) {
    return (uint32_t)(r * 128 + ((c ^ (r & 7)) << 4));
}

#define CP_ASYNC16(dst, src) \
    asm volatile("cp.async.cg.shared.global [%0], [%1], 16;" :: "r"(dst), "l"(src))
#define CP_COMMIT() asm volatile("cp.async.commit_group;" ::: "memory")
#define CP_WAIT1()  asm volatile("cp.async.wait_group 1;" ::: "memory")
#define CP_WAIT0()  asm volatile("cp.async.wait_group 0;" ::: "memory")

#define LDSM_X4(r0, r1, r2, r3, addr)                                      \
    asm volatile("ldmatrix.sync.aligned.m8n8.x4.shared.b16 {%0,%1,%2,%3}, [%4];" \
        : "=r"(r0), "=r"(r1), "=r"(r2), "=r"(r3) : "r"(addr))

__device__ __forceinline__ void mma_f16(float& c0, float& c1, float& c2, float& c3,
                                        uint32_t a0, uint32_t a1, uint32_t a2, uint32_t a3,
                                        uint32_t b0, uint32_t b1) {
    asm volatile(
        "mma.sync.aligned.m16n8k16.row.col.f32.f16.f16.f32 "
        "{%0,%1,%2,%3}, {%4,%5,%6,%7}, {%8,%9}, {%0,%1,%2,%3};"
        : "+f"(c0), "+f"(c1), "+f"(c2), "+f"(c3)
        : "r"(a0), "r"(a1), "r"(a2), "r"(a3), "r"(b0), "r"(b1));
}

// exp on FMA/ALU pipes (no MUFU)
__device__ __forceinline__ float fast_exp(float x) {
    float t = fmaxf(x * 1.4426950408889634f, -126.0f);
    float z = t + 12582912.0f;
    int   n = __float_as_int(z) - 0x4B400000;
    float f = t - (z - 12582912.0f);
    float p =            1.3333558146e-3f;
    p = fmaf(p, f, 9.6181291076e-3f);
    p = fmaf(p, f, 5.5504108664e-2f);
    p = fmaf(p, f, 2.4022650696e-1f);
    p = fmaf(p, f, 6.9314718056e-1f);
    p = fmaf(p, f, 1.0f);
    return __int_as_float(__float_as_int(p) + (n << 23));
}

// MODE 0: Dh = A@B^T + bias; cols<1024 scaled by oscale (merged q|k proj)
// MODE 3: Dh = A@B^T + bias[m]                 (vT = Wv @ x_b^T)
// MODE 1: Dh = exp(A@B^T), causal->0, + row partial sums (triangular grid)
// MODE 2: Df = (A@B^T) / rowsum_from_partials  (out; K clipped, bm reversed)
// All geometry is compile-time per MODE (lda == ldb in every launch).
template <int MODE>
__global__ void __launch_bounds__(NTHREADS, 2)
tgemm(const __half* __restrict__ A, const __half* __restrict__ B,
      const float* __restrict__ bias, const float* __restrict__ bias2,
      void* __restrict__ Cout, float* __restrict__ partial,
      float oscale)
{
    constexpr int  LDA  = (MODE == 0 || MODE == 3) ? CDIM : 2 * CDIM;
    constexpr int  NTOT = (MODE == 2) ? CDIM : 2 * CDIM;     // MODE1: SEQ==2*CDIM
    constexpr int  KEXT = (MODE == 2) ? SEQ : CDIM;
    constexpr long SA = (MODE == 1) ? (long)SEQ * 2 * CDIM
                       : (MODE == 2) ? (long)SEQ * SEQ : 0L;
    constexpr long SB = (MODE == 3) ? (long)SEQ * CDIM
                       : (MODE == 1) ? (long)SEQ * 2 * CDIM
                       : (MODE == 2) ? (long)CDIM * SEQ : 0L;
    constexpr long SC = (MODE == 3) ? (long)CDIM * SEQ
                       : (MODE == 1) ? (long)SEQ * SEQ
                       : (MODE == 2) ? (long)SEQ * CDIM : 0L;

    int bn, bm;
    const int bz = blockIdx.z;
    if (MODE == 1) {
        // triangular decode: linear tile t -> (bm, bn), bn <= bm (no dead CTAs)
        const int t = blockIdx.x;
        bm = (int)((__fsqrt_rn(8.0f * (float)t + 1.0f) - 1.0f) * 0.5f);
        while (bm * (bm + 1) / 2 > t) bm--;
        while ((bm + 1) * (bm + 2) / 2 <= t) bm++;
        bn = t - bm * (bm + 1) / 2;
    } else {
        bn = blockIdx.x;
        bm = (MODE == 2) ? ((int)gridDim.y - 1 - (int)blockIdx.y)
                         : (int)blockIdx.y;
    }

    extern __shared__ __align__(16) char sm[];

    const int tid  = threadIdx.x;
    const int wid  = tid >> 5, lane = tid & 31;
    const int wm   = wid >> 2;             // 0..1 -> 64-row slab
    const int wn   = wid & 3;              // 0..3 -> 32-col slab
    const int tr   = lane >> 2;            // 0..7
    const int tc   = lane & 3;             // 0..3

    int Keff = KEXT;
    if (MODE == 2) { int kl = (bm + 1) * BM; if (kl < Keff) Keff = kl; }
    const int chunks = Keff / BK;          // >= 2 always

    const uint32_t sbase = smem_u32(sm);

    // ---- cp.async state ----
    const int ldr = tid >> 3, ldc = tid & 7;
    const __half* aSrc = A + (long)bz * SA + (long)(bm * BM + ldr) * LDA + ldc * 8;
    const __half* bSrc = B + (long)bz * SB + (long)(bn * BN + ldr) * LDA + ldc * 8;
    const uint32_t dA0 = sbase + swz(ldr, ldc);

    uint32_t issueOff = 0;
    uint32_t srcAdv = 0;

    auto issue = [&]() {
        CP_ASYNC16(dA0 + issueOff,             aSrc + srcAdv);
        CP_ASYNC16(dA0 + issueOff + 32 * 128,  aSrc + srcAdv + 32 * LDA);
        CP_ASYNC16(dA0 + issueOff + 64 * 128,  aSrc + srcAdv + 64 * LDA);
        CP_ASYNC16(dA0 + issueOff + 96 * 128,  aSrc + srcAdv + 96 * LDA);
        const uint32_t bOff = issueOff + NSTAGE * STAGE_BYTES;
        CP_ASYNC16(dA0 + bOff,                 bSrc + srcAdv);
        CP_ASYNC16(dA0 + bOff + 32 * 128,      bSrc + srcAdv + 32 * LDA);
        CP_ASYNC16(dA0 + bOff + 64 * 128,      bSrc + srcAdv + 64 * LDA);
        CP_ASYNC16(dA0 + bOff + 96 * 128,      bSrc + srcAdv + 96 * LDA);
        CP_COMMIT();
        srcAdv += BK;
        issueOff = (issueOff == 2 * STAGE_BYTES) ? 0u : issueOff + STAGE_BYTES;
    };

    // ---- ldmatrix bases (stage 0); per-ks addr = base ^ (ks<<5) ----
    uint32_t ldA[4], ldB[2];
#pragma unroll
    for (int mf = 0; mf < 4; mf++)
        ldA[mf] = sbase + swz(wm * 64 + mf * 16 + (lane & 15), lane >> 4);
#pragma unroll
    for (int np = 0; np < 2; np++)
        ldB[np] = sbase + NSTAGE * STAGE_BYTES
                + swz(wn * 32 + np * 16 + (lane & 15), lane >> 4);

    float acc[4][4][4];
#pragma unroll
    for (int i = 0; i < 4; i++)
#pragma unroll
        for (int j = 0; j < 4; j++)
#pragma unroll
            for (int e = 0; e < 4; e++) acc[i][j][e] = 0.0f;

    issue(); issue();

    int stage = 0;
    for (int i = 0; i < chunks; i++) {
        if (i + 1 < chunks) CP_WAIT1(); else CP_WAIT0();
        __syncthreads();

#pragma unroll
        for (int ks = 0; ks < 4; ks++) {
            const uint32_t kx = (uint32_t)(ks << 5);
            uint32_t af[4][4], bf[2][4];
#pragma unroll
            for (int mf = 0; mf < 4; mf++)
                LDSM_X4(af[mf][0], af[mf][1], af[mf][2], af[mf][3], ldA[mf] ^ kx);
#pragma unroll
            for (int np = 0; np < 2; np++)
                LDSM_X4(bf[np][0], bf[np][1], bf[np][2], bf[np][3], ldB[np] ^ kx);
#pragma unroll
            for (int mf = 0; mf < 4; mf++)
#pragma unroll
                for (int nf = 0; nf < 4; nf++) {
                    const int np = nf >> 1, sub = nf & 1;
                    mma_f16(acc[mf][nf][0], acc[mf][nf][1],
                            acc[mf][nf][2], acc[mf][nf][3],
                            af[mf][0], af[mf][1], af[mf][2], af[mf][3],
                            bf[np][sub], bf[np][sub + 2]);
                }
        }

        if (i + 2 < chunks) issue();
        const int32_t delta = (stage == 2) ? -(2 * STAGE_BYTES) : STAGE_BYTES;
        stage = (stage == 2) ? 0 : stage + 1;
#pragma unroll
        for (int mf = 0; mf < 4; mf++) ldA[mf] += delta;
        ldB[0] += delta; ldB[1] += delta;
    }

    // ---- epilogue ----
    float* srow4 = (float*)(sm + SROW_OFF);    // [128][4] per-(row, wn) sums
    const bool is_q = (MODE == 0) && (bn * BN < CDIM);

#pragma unroll
    for (int mf = 0; mf < 4; mf++) {
        const int r0 = bm * BM + wm * 64 + mf * 16 + tr;
        const int r1 = r0 + 8;
        float rb0 = 0.0f, rb1 = 0.0f;
        if (MODE == 3) { rb0 = __ldg(&bias[r0]); rb1 = __ldg(&bias[r1]); }
        if (MODE == 2) {
            // rowsum from the 16 partials (unwritten entries are exactly 0)
            const float4* p0 = (const float4*)&partial[((long)bz * SEQ + r0) * 16];
            const float4* p1 = (const float4*)&partial[((long)bz * SEQ + r1) * 16];
            float s0 = 0.0f, s1 = 0.0f;
#pragma unroll
            for (int j = 0; j < 4; j++) {
                float4 a = __ldg(&p0[j]), b = __ldg(&p1[j]);
                s0 += (a.x + a.y) + (a.z + a.w);
                s1 += (b.x + b.y) + (b.z + b.w);
            }
            rb0 = 1.0f / s0;
            rb1 = 1.0f / s1;
        }
        float rs0 = 0.0f, rs1 = 0.0f;
#pragma unroll
        for (int nf = 0; nf < 4; nf++) {
            const int c = bn * BN + wn * 32 + nf * 8 + 2 * tc;
            float v0 = acc[mf][nf][0], v1 = acc[mf][nf][1];
            float v2 = acc[mf][nf][2], v3 = acc[mf][nf][3];

            if (MODE == 0) {
                const float* bp = is_q ? bias : bias2;
                const int cc = is_q ? c : c - CDIM;
                const float b0 = __ldg(&bp[cc]), b1 = __ldg(&bp[cc + 1]);
                const float sc = is_q ? oscale : 1.0f;
                v0 = (v0 + b0) * sc; v1 = (v1 + b1) * sc;
                v2 = (v2 + b0) * sc; v3 = (v3 + b1) * sc;
            }
            if (MODE == 3) { v0 += rb0; v1 += rb0; v2 += rb1; v3 += rb1; }
            if (MODE == 1) {
                v0 = (c     > r0) ? 0.0f : fast_exp(v0);
                v1 = (c + 1 > r0) ? 0.0f : fast_exp(v1);
                v2 = (c     > r1) ? 0.0f : fast_exp(v2);
                v3 = (c + 1 > r1) ? 0.0f : fast_exp(v3);
                rs0 += v0 + v1; rs1 += v2 + v3;
            }

            if (MODE != 2) {
                __half* Ch = (__half*)Cout + (long)bz * SC;
                *(__half2*)&Ch[(long)r0 * NTOT + c] = __floats2half2_rn(v0, v1);
                *(__half2*)&Ch[(long)r1 * NTOT + c] = __floats2half2_rn(v2, v3);
            } else {
                float* Cf = (float*)Cout + (long)bz * SC;
                *(float2*)&Cf[(long)r0 * NTOT + c] = make_float2(v0 * rb0, v1 * rb0);
                *(float2*)&Cf[(long)r1 * NTOT + c] = make_float2(v2 * rb1, v3 * rb1);
            }
        }
        if (MODE == 1) {
            rs0 += __shfl_xor_sync(0xffffffffu, rs0, 1);
            rs0 += __shfl_xor_sync(0xffffffffu, rs0, 2);
            rs1 += __shfl_xor_sync(0xffffffffu, rs1, 1);
            rs1 += __shfl_xor_sync(0xffffffffu, rs1, 2);
            if (tc == 0) {
                const int lr0 = wm * 64 + mf * 16 + tr;
                srow4[lr0 * 4 + wn]       = rs0;
                srow4[(lr0 + 8) * 4 + wn] = rs1;
            }
        }
    }

    if (MODE == 1) {
        __syncthreads();
        if (tid < 128) {
            const float s = srow4[tid * 4] + srow4[tid * 4 + 1]
                          + srow4[tid * 4 + 2] + srow4[tid * 4 + 3];
            partial[((long)bz * SEQ + bm * BM + tid) * 16 + bn] = s;
        }
    }
}

// fused fp32 -> fp16 conversion of x, Wq, Wk, Wv (one launch)
#define NX4 (1L << 22)          // B*T*C/4
#define NW4 (1L << 18)          // C*C/4
__global__ void __launch_bounds__(256)
f2h_all(const float4* __restrict__ x,  const float4* __restrict__ wq,
        const float4* __restrict__ wk, const float4* __restrict__ wv,
        __half2* __restrict__ xh, __half2* __restrict__ wh)
{
    const long i = (long)blockIdx.x * 256 + threadIdx.x;
    const float4* src;
    __half2* dst;
    long j;
    if (i < NX4) { src = x; dst = xh; j = i; }
    else {
        const long r = i - NX4;
        const int  w = (int)(r >> 18);
        j = r & (NW4 - 1);
        src = (w == 0) ? wq : (w == 1) ? wk : wv;
        dst = wh + w * NW4 * 2;
    }
    float4 v = src[j];
    dst[2 * j]     = __floats2half2_rn(v.x, v.y);
    dst[2 * j + 1] = __floats2half2_rn(v.z, v.w);
}

extern "C" void kernel_launch(void* const* d_in, const int* in_sizes, int n_in,
                              void* d_out, int out_size)
{
    const float* x  = (const float*)d_in[0];
    const float* Wq = (const float*)d_in[1];
    const float* bq = (const float*)d_in[2];
    const float* Wk = (const float*)d_in[3];
    const float* bk = (const float*)d_in[4];
    const float* Wv = (const float*)d_in[5];
    const float* bv = (const float*)d_in[6];
    float* out = (float*)d_out;

    __half *xh, *wh, *qk, *vt, *p;
    float *part;
    cudaGetSymbolAddress((void**)&xh,   g_xh);
    cudaGetSymbolAddress((void**)&wh,   g_wh);
    cudaGetSymbolAddress((void**)&qk,   g_qk);
    cudaGetSymbolAddress((void**)&vt,   g_vt);
    cudaGetSymbolAddress((void**)&p,    g_p);
    cudaGetSymbolAddress((void**)&part, g_partial);
    __half* wvh = wh + 2L * CDIM * CDIM;

    static cudaStream_t s2 = nullptr;
    static cudaEvent_t evFork = nullptr, evJoin = nullptr;
    static bool attr_done = false;
    if (!attr_done) {
        cudaFuncSetAttribute(tgemm<0>, cudaFuncAttributeMaxDynamicSharedMemorySize, SMEM_SZ);
        cudaFuncSetAttribute(tgemm<1>, cudaFuncAttributeMaxDynamicSharedMemorySize, SMEM_SZ);
        cudaFuncSetAttribute(tgemm<2>, cudaFuncAttributeMaxDynamicSharedMemorySize, SMEM_SZ);
        cudaFuncSetAttribute(tgemm<3>, cudaFuncAttributeMaxDynamicSharedMemorySize, SMEM_SZ);
        cudaStreamCreateWithFlags(&s2, cudaStreamNonBlocking);
        cudaEventCreateWithFlags(&evFork, cudaEventDisableTiming);
        cudaEventCreateWithFlags(&evJoin, cudaEventDisableTiming);
        attr_done = true;
    }

    const int T = SEQ, C = CDIM, Bsz = BATCH;
    const int M = Bsz * T;
    const float scale = rsqrtf((float)C);   // 1/32, folded into q half

    // fused fp32 -> fp16 prep (stream 0)
    {
        const long total = NX4 + 3 * NW4;
        f2h_all<<<(unsigned)((total + 255) / 256), 256>>>(
            (const float4*)x, (const float4*)Wq, (const float4*)Wk,
            (const float4*)Wv, (__half2*)xh, (__half2*)wh);
    }

    // fork: vT projection on s2 (depends only on f2h output)
    cudaEventRecord(evFork, 0);
    cudaStreamWaitEvent(s2, evFork, 0);
    dim3 gV(T / BN, C / BM, Bsz);                        // (16, 8, 8)
    tgemm<3><<<gV, NTHREADS, SMEM_SZ, s2>>>(wvh, xh, bv, nullptr, vt,
                                            nullptr, 1.0f);
    cudaEventRecord(evJoin, s2);

    // stream 0: merged q|k projection, then S
    dim3 gP(2 * C / BN, M / BM, 1);                      // (16, 128)
    tgemm<0><<<gP, NTHREADS, SMEM_SZ>>>(xh, wh, bq, bk, qk, nullptr, scale);

    // P~ = exp(q k^T), triangular grid (136 live tiles per batch)
    dim3 gS(16 * 17 / 2, 1, Bsz);                        // (136, 1, 8)
    tgemm<1><<<gS, NTHREADS, SMEM_SZ>>>(qk, qk + C, nullptr, nullptr, p, part,
                                        1.0f);

    // join vT before PV
    cudaStreamWaitEvent(0, evJoin, 0);

    // out = (P~ @ vT^T) / rowsum, K clipped; longest tiles first
    dim3 gO(C / BN, T / BM, Bsz);                        // (8, 16, 8)
    tgemm<2><<<gO, NTHREADS, SMEM_SZ>>>(p, vt, nullptr, nullptr, out, part,
                                        1.0f);
}

// round 15
// speedup vs baseline: 1.0065x; 1.0065x over previous
#include <cuda_runtime.h>
#include <cuda_fp16.h>
#include <stdint.h>

// B=8, T=2048, C=1024, fp32 in/out.
//  qk = x @ [Wq;Wk]^T (+bias, q-half scaled 1/32), fp16, one GEMM
//  vT[b] = Wv @ x_b^T + bv, fp16
//  P~ = exp(q k^T) causal->0 (fused epilogue + fused row partial sums)
//  inv = 1/rowsum(P~);  out = (P~ @ vT^T) * inv[row]
// R15: exact revert to the R13 champion (540.9 us). R14's triangular grid
// and epilogue-rowsum both regressed; early-exit dead CTAs and the tiny
// inv kernel are cheaper than their replacements. mma.sync plateau
// (~330 TF/s eff) confirmed across 7 structural variants.

#define BATCH 8
#define SEQ   2048
#define CDIM  1024

__device__ __align__(16) __half g_xh[(long)BATCH * SEQ * CDIM];
__device__ __align__(16) __half g_wh[3][(long)CDIM * CDIM];   // Wq,Wk,Wv
__device__ __align__(16) __half g_qk[(long)BATCH * SEQ * 2 * CDIM]; // q | k
__device__ __align__(16) __half g_vt[(long)BATCH * CDIM * SEQ];
__device__ __align__(16) __half g_p [(long)BATCH * SEQ * SEQ];
__device__ __align__(16) float  g_partial[(long)BATCH * SEQ * 16];
__device__ __align__(16) float  g_inv[(long)BATCH * SEQ];

#define BM 128
#define BN 128
#define BK 64                  // 64 fp16 = 128 B per smem row
#define NTHREADS 256
#define NSTAGE 3
#define STAGE_BYTES 16384

#define SROW_OFF (NSTAGE * 32768)
#define SMEM_SZ (NSTAGE * 32768 + 2048)    // 100352 B -> 2 CTAs/SM

__device__ __forceinline__ uint32_t smem_u32(const void* p) {
    uint32_t r;
    asm("{ .reg .u64 t; cvta.to.shared.u64 t, %1; cvt.u32.u64 %0, t; }"
        : "=r"(r) : "l"(p));
    return r;
}

// swizzled byte offset of 16B chunk c (0..7) in 128B row r
__device__ __forceinline__ uint32_t swz(int r, int c) {
    return (uint32_t)(r * 128 + ((c ^ (r & 7)) << 4));
}

#define CP_ASYNC16(dst, src) \
    asm volatile("cp.async.cg.shared.global [%0], [%1], 16;" :: "r"(dst), "l"(src))
#define CP_COMMIT() asm volatile("cp.async.commit_group;" ::: "memory")
#define CP_WAIT1()  asm volatile("cp.async.wait_group 1;" ::: "memory")
#define CP_WAIT0()  asm volatile("cp.async.wait_group 0;" ::: "memory")

#define LDSM_X4(r0, r1, r2, r3, addr)                                      \
    asm volatile("ldmatrix.sync.aligned.m8n8.x4.shared.b16 {%0,%1,%2,%3}, [%4];" \
        : "=r"(r0), "=r"(r1), "=r"(r2), "=r"(r3) : "r"(addr))

__device__ __forceinline__ void mma_f16(float& c0, float& c1, float& c2, float& c3,
                                        uint32_t a0, uint32_t a1, uint32_t a2, uint32_t a3,
                                        uint32_t b0, uint32_t b1) {
    asm volatile(
        "mma.sync.aligned.m16n8k16.row.col.f32.f16.f16.f32 "
        "{%0,%1,%2,%3}, {%4,%5,%6,%7}, {%8,%9}, {%0,%1,%2,%3};"
        : "+f"(c0), "+f"(c1), "+f"(c2), "+f"(c3)
        : "r"(a0), "r"(a1), "r"(a2), "r"(a3), "r"(b0), "r"(b1));
}

// exp on FMA/ALU pipes (no MUFU)
__device__ __forceinline__ float fast_exp(float x) {
    float t = fmaxf(x * 1.4426950408889634f, -126.0f);
    float z = t + 12582912.0f;
    int   n = __float_as_int(z) - 0x4B400000;
    float f = t - (z - 12582912.0f);
    float p =            1.3333558146e-3f;
    p = fmaf(p, f, 9.6181291076e-3f);
    p = fmaf(p, f, 5.5504108664e-2f);
    p = fmaf(p, f, 2.4022650696e-1f);
    p = fmaf(p, f, 6.9314718056e-1f);
    p = fmaf(p, f, 1.0f);
    return __int_as_float(__float_as_int(p) + (n << 23));
}

// MODE 0: Dh = A@B^T + bias; cols<1024 scaled by oscale (merged q|k proj)
// MODE 3: Dh = A@B^T + bias[m]                 (vT = Wv @ x_b^T)
// MODE 1: Dh = exp(A@B^T), causal->0, + row partial sums (P~)
// MODE 2: Df = (A@B^T) * inv[m]                (out; K clipped, bm reversed)
// All geometry is compile-time per MODE (lda == ldb in every launch).
template <int MODE>
__global__ void __launch_bounds__(NTHREADS, 2)
tgemm(const __half* __restrict__ A, const __half* __restrict__ B,
      const float* __restrict__ bias, const float* __restrict__ bias2,
      void* __restrict__ Cout, float* __restrict__ partial,
      const float* __restrict__ inv, float oscale)
{
    constexpr int  LDA  = (MODE == 0 || MODE == 3) ? CDIM : 2 * CDIM;
    constexpr int  NTOT = (MODE == 2) ? CDIM : 2 * CDIM;     // MODE1: SEQ==2*CDIM
    constexpr int  KEXT = (MODE == 2) ? SEQ : CDIM;
    constexpr long SA = (MODE == 1) ? (long)SEQ * 2 * CDIM
                       : (MODE == 2) ? (long)SEQ * SEQ : 0L;
    constexpr long SB = (MODE == 3) ? (long)SEQ * CDIM
                       : (MODE == 1) ? (long)SEQ * 2 * CDIM
                       : (MODE == 2) ? (long)CDIM * SEQ : 0L;
    constexpr long SC = (MODE == 3) ? (long)CDIM * SEQ
                       : (MODE == 1) ? (long)SEQ * SEQ
                       : (MODE == 2) ? (long)SEQ * CDIM : 0L;

    const int bn = blockIdx.x;
    const int bm = (MODE == 2) ? ((int)gridDim.y - 1 - (int)blockIdx.y)
                               : (int)blockIdx.y;
    const int bz = blockIdx.z;
    if (MODE == 1 && bn > bm) return;      // fully-masked tile, never read

    extern __shared__ __align__(16) char sm[];

    const int tid  = threadIdx.x;
    const int wid  = tid >> 5, lane = tid & 31;
    const int wm   = wid >> 2;             // 0..1 -> 64-row slab
    const int wn   = wid & 3;              // 0..3 -> 32-col slab
    const int tr   = lane >> 2;            // 0..7
    const int tc   = lane & 3;             // 0..3

    int Keff = KEXT;
    if (MODE == 2) { int kl = (bm + 1) * BM; if (kl < Keff) Keff = kl; }
    const int chunks = Keff / BK;          // >= 2 always

    const uint32_t sbase = smem_u32(sm);

    // ---- cp.async state ----
    const int ldr = tid >> 3, ldc = tid & 7;
    const __half* aSrc = A + (long)bz * SA + (long)(bm * BM + ldr) * LDA + ldc * 8;
    const __half* bSrc = B + (long)bz * SB + (long)(bn * BN + ldr) * LDA + ldc * 8;
    const uint32_t dA0 = sbase + swz(ldr, ldc);

    uint32_t issueOff = 0;
    uint32_t srcAdv = 0;

    auto issue = [&]() {
        CP_ASYNC16(dA0 + issueOff,             aSrc + srcAdv);
        CP_ASYNC16(dA0 + issueOff + 32 * 128,  aSrc + srcAdv + 32 * LDA);
        CP_ASYNC16(dA0 + issueOff + 64 * 128,  aSrc + srcAdv + 64 * LDA);
        CP_ASYNC16(dA0 + issueOff + 96 * 128,  aSrc + srcAdv + 96 * LDA);
        const uint32_t bOff = issueOff + NSTAGE * STAGE_BYTES;
        CP_ASYNC16(dA0 + bOff,                 bSrc + srcAdv);
        CP_ASYNC16(dA0 + bOff + 32 * 128,      bSrc + srcAdv + 32 * LDA);
        CP_ASYNC16(dA0 + bOff + 64 * 128,      bSrc + srcAdv + 64 * LDA);
        CP_ASYNC16(dA0 + bOff + 96 * 128,      bSrc + srcAdv + 96 * LDA);
        CP_COMMIT();
        srcAdv += BK;
        issueOff = (issueOff == 2 * STAGE_BYTES) ? 0u : issueOff + STAGE_BYTES;
    };

    // ---- ldmatrix bases (stage 0); per-ks addr = base ^ (ks<<5) ----
    uint32_t ldA[4], ldB[2];
#pragma unroll
    for (int mf = 0; mf < 4; mf++)
        ldA[mf] = sbase + swz(wm * 64 + mf * 16 + (lane & 15), lane >> 4);
#pragma unroll
    for (int np = 0; np < 2; np++)
        ldB[np] = sbase + NSTAGE * STAGE_BYTES
                + swz(wn * 32 + np * 16 + (lane & 15), lane >> 4);

    float acc[4][4][4];
#pragma unroll
    for (int i = 0; i < 4; i++)
#pragma unroll
        for (int j = 0; j < 4; j++)
#pragma unroll
            for (int e = 0; e < 4; e++) acc[i][j][e] = 0.0f;

    issue(); issue();

    int stage = 0;
    for (int i = 0; i < chunks; i++) {
        if (i + 1 < chunks) CP_WAIT1(); else CP_WAIT0();
        __syncthreads();

#pragma unroll
        for (int ks = 0; ks < 4; ks++) {
            const uint32_t kx = (uint32_t)(ks << 5);
            uint32_t af[4][4], bf[2][4];
#pragma unroll
            for (int mf = 0; mf < 4; mf++)
                LDSM_X4(af[mf][0], af[mf][1], af[mf][2], af[mf][3], ldA[mf] ^ kx);
#pragma unroll
            for (int np = 0; np < 2; np++)
                LDSM_X4(bf[np][0], bf[np][1], bf[np][2], bf[np][3], ldB[np] ^ kx);
#pragma unroll
            for (int mf = 0; mf < 4; mf++)
#pragma unroll
                for (int nf = 0; nf < 4; nf++) {
                    const int np = nf >> 1, sub = nf & 1;
                    mma_f16(acc[mf][nf][0], acc[mf][nf][1],
                            acc[mf][nf][2], acc[mf][nf][3],
                            af[mf][0], af[mf][1], af[mf][2], af[mf][3],
                            bf[np][sub], bf[np][sub + 2]);
                }
        }

        if (i + 2 < chunks) issue();
        const int32_t delta = (stage == 2) ? -(2 * STAGE_BYTES) : STAGE_BYTES;
        stage = (stage == 2) ? 0 : stage + 1;
#pragma unroll
        for (int mf = 0; mf < 4; mf++) ldA[mf] += delta;
        ldB[0] += delta; ldB[1] += delta;
    }

    // ---- epilogue ----
    float* srow4 = (float*)(sm + SROW_OFF);    // [128][4] per-(row, wn) sums
    const bool is_q = (MODE == 0) && (bn * BN < CDIM);

#pragma unroll
    for (int mf = 0; mf < 4; mf++) {
        const int r0 = bm * BM + wm * 64 + mf * 16 + tr;
        const int r1 = r0 + 8;
        float rb0 = 0.0f, rb1 = 0.0f;
        if (MODE == 3) { rb0 = __ldg(&bias[r0]); rb1 = __ldg(&bias[r1]); }
        if (MODE == 2) { rb0 = __ldg(&inv[(long)bz * SEQ + r0]);
                         rb1 = __ldg(&inv[(long)bz * SEQ + r1]); }
        float rs0 = 0.0f, rs1 = 0.0f;
#pragma unroll
        for (int nf = 0; nf < 4; nf++) {
            const int c = bn * BN + wn * 32 + nf * 8 + 2 * tc;
            float v0 = acc[mf][nf][0], v1 = acc[mf][nf][1];
            float v2 = acc[mf][nf][2], v3 = acc[mf][nf][3];

            if (MODE == 0) {
                const float* bp = is_q ? bias : bias2;
                const int cc = is_q ? c : c - CDIM;
                const float b0 = __ldg(&bp[cc]), b1 = __ldg(&bp[cc + 1]);
                const float sc = is_q ? oscale : 1.0f;
                v0 = (v0 + b0) * sc; v1 = (v1 + b1) * sc;
                v2 = (v2 + b0) * sc; v3 = (v3 + b1) * sc;
            }
            if (MODE == 3) { v0 += rb0; v1 += rb0; v2 += rb1; v3 += rb1; }
            if (MODE == 1) {
                v0 = (c     > r0) ? 0.0f : fast_exp(v0);
                v1 = (c + 1 > r0) ? 0.0f : fast_exp(v1);
                v2 = (c     > r1) ? 0.0f : fast_exp(v2);
                v3 = (c + 1 > r1) ? 0.0f : fast_exp(v3);
                rs0 += v0 + v1; rs1 += v2 + v3;
            }

            if (MODE != 2) {
                __half* Ch = (__half*)Cout + (long)bz * SC;
                *(__half2*)&Ch[(long)r0 * NTOT + c] = __floats2half2_rn(v0, v1);
                *(__half2*)&Ch[(long)r1 * NTOT + c] = __floats2half2_rn(v2, v3);
            } else {
                float* Cf = (float*)Cout + (long)bz * SC;
                *(float2*)&Cf[(long)r0 * NTOT + c] = make_float2(v0 * rb0, v1 * rb0);
                *(float2*)&Cf[(long)r1 * NTOT + c] = make_float2(v2 * rb1, v3 * rb1);
            }
        }
        if (MODE == 1) {
            rs0 += __shfl_xor_sync(0xffffffffu, rs0, 1);
            rs0 += __shfl_xor_sync(0xffffffffu, rs0, 2);
            rs1 += __shfl_xor_sync(0xffffffffu, rs1, 1);
            rs1 += __shfl_xor_sync(0xffffffffu, rs1, 2);
            if (tc == 0) {
                const int lr0 = wm * 64 + mf * 16 + tr;
                srow4[lr0 * 4 + wn]       = rs0;
                srow4[(lr0 + 8) * 4 + wn] = rs1;
            }
        }
    }

    if (MODE == 1) {
        __syncthreads();
        if (tid < 128) {
            const float s = srow4[tid * 4] + srow4[tid * 4 + 1]
                          + srow4[tid * 4 + 2] + srow4[tid * 4 + 3];
            partial[((long)bz * SEQ + bm * BM + tid) * 16 + bn] = s;
        }
    }
}

// fused fp32 -> fp16 conversion of x, Wq, Wk, Wv (one launch)
#define NX4 (1L << 22)          // B*T*C/4
#define NW4 (1L << 18)          // C*C/4
__global__ void __launch_bounds__(256)
f2h_all(const float4* __restrict__ x,  const float4* __restrict__ wq,
        const float4* __restrict__ wk, const float4* __restrict__ wv,
        __half2* __restrict__ xh, __half2* __restrict__ wh)
{
    const long i = (long)blockIdx.x * 256 + threadIdx.x;
    const float4* src;
    __half2* dst;
    long j;
    if (i < NX4) { src = x; dst = xh; j = i; }
    else {
        const long r = i - NX4;
        const int  w = (int)(r >> 18);
        j = r & (NW4 - 1);
        src = (w == 0) ? wq : (w == 1) ? wk : wv;
        dst = wh + w * NW4 * 2;
    }
    float4 v = src[j];
    dst[2 * j]     = __floats2half2_rn(v.x, v.y);
    dst[2 * j + 1] = __floats2half2_rn(v.z, v.w);
}

// inv[b,t] = 1 / sum of row partials
__global__ void __launch_bounds__(256)
inv_kernel(const float* __restrict__ partial, float* __restrict__ inv_out)
{
    const int idx = blockIdx.x * 256 + threadIdx.x;
    const int t = idx & (SEQ - 1);
    const int nb = (t >> 7) + 1;
    const float* pp = partial + (long)idx * 16;
    float s = 0.0f;
    for (int j = 0; j < nb; j++) s += pp[j];
    inv_out[idx] = 1.0f / s;
}

extern "C" void kernel_launch(void* const* d_in, const int* in_sizes, int n_in,
                              void* d_out, int out_size)
{
    const float* x  = (const float*)d_in[0];
    const float* Wq = (const float*)d_in[1];
    const float* bq = (const float*)d_in[2];
    const float* Wk = (const float*)d_in[3];
    const float* bk = (const float*)d_in[4];
    const float* Wv = (const float*)d_in[5];
    const float* bv = (const float*)d_in[6];
    float* out = (float*)d_out;

    __half *xh, *wh, *qk, *vt, *p;
    float *part, *inv;
    cudaGetSymbolAddress((void**)&xh,   g_xh);
    cudaGetSymbolAddress((void**)&wh,   g_wh);
    cudaGetSymbolAddress((void**)&qk,   g_qk);
    cudaGetSymbolAddress((void**)&vt,   g_vt);
    cudaGetSymbolAddress((void**)&p,    g_p);
    cudaGetSymbolAddress((void**)&part, g_partial);
    cudaGetSymbolAddress((void**)&inv,  g_inv);
    __half* wvh = wh + 2L * CDIM * CDIM;

    static cudaStream_t s2 = nullptr;
    static cudaEvent_t evFork = nullptr, evJoin = nullptr;
    static bool attr_done = false;
    if (!attr_done) {
        cudaFuncSetAttribute(tgemm<0>, cudaFuncAttributeMaxDynamicSharedMemorySize, SMEM_SZ);
        cudaFuncSetAttribute(tgemm<1>, cudaFuncAttributeMaxDynamicSharedMemorySize, SMEM_SZ);
        cudaFuncSetAttribute(tgemm<2>, cudaFuncAttributeMaxDynamicSharedMemorySize, SMEM_SZ);
        cudaFuncSetAttribute(tgemm<3>, cudaFuncAttributeMaxDynamicSharedMemorySize, SMEM_SZ);
        cudaStreamCreateWithFlags(&s2, cudaStreamNonBlocking);
        cudaEventCreateWithFlags(&evFork, cudaEventDisableTiming);
        cudaEventCreateWithFlags(&evJoin, cudaEventDisableTiming);
        attr_done = true;
    }

    const int T = SEQ, C = CDIM, Bsz = BATCH;
    const int M = Bsz * T;
    const float scale = rsqrtf((float)C);   // 1/32, folded into q half

    // fused fp32 -> fp16 prep (stream 0)
    {
        const long total = NX4 + 3 * NW4;
        f2h_all<<<(unsigned)((total + 255) / 256), 256>>>(
            (const float4*)x, (const float4*)Wq, (const float4*)Wk,
            (const float4*)Wv, (__half2*)xh, (__half2*)wh);
    }

    // fork: vT projection on s2 (depends only on f2h output)
    cudaEventRecord(evFork, 0);
    cudaStreamWaitEvent(s2, evFork, 0);
    dim3 gV(T / BN, C / BM, Bsz);                        // (16, 8, 8)
    tgemm<3><<<gV, NTHREADS, SMEM_SZ, s2>>>(wvh, xh, bv, nullptr, vt,
                                            nullptr, nullptr, 1.0f);
    cudaEventRecord(evJoin, s2);

    // stream 0: merged q|k projection, then S
    dim3 gP(2 * C / BN, M / BM, 1);                      // (16, 128)
    tgemm<0><<<gP, NTHREADS, SMEM_SZ>>>(xh, wh, bq, bk, qk, nullptr, nullptr, scale);

    dim3 gS(T / BN, T / BM, Bsz);                        // (16, 16, 8)
    tgemm<1><<<gS, NTHREADS, SMEM_SZ>>>(qk, qk + C, nullptr, nullptr, p, part,
                                        nullptr, 1.0f);

    // inv = 1 / rowsum(P~)
    inv_kernel<<<(Bsz * T) / 256, 256>>>(part, inv);

    // join vT before PV
    cudaStreamWaitEvent(0, evJoin, 0);

    // out = (P~ @ vT^T) * inv[row], K clipped; longest tiles first
    dim3 gO(C / BN, T / BM, Bsz);                        // (8, 16, 8)
    tgemm<2><<<gO, NTHREADS, SMEM_SZ>>>(p, vt, nullptr, nullptr, out, nullptr,
                                        inv, 1.0f);
}